// round 3
// baseline (speedup 1.0000x reference)
#include <cuda_runtime.h>
#include <cstdint>
#include <cstddef>

// Problem constants
#define T_STEPS 2048
#define BATCH   256
#define FEAT    64
#define HID     256
#define KDIM    320            // FEAT + HID
#define NB      4              // batches per cluster
#define THREADS 512
#define NSLICE  4              // k-slices per CTA (s = tid & 3)
#define KSLICE  80             // k per slice
#define NPAIR   40             // f32x2 pairs per slice

// comb smem layout (per buffer): 4 slices; each slice = 40 pairs * 4 batches * 2 halves
// slice stride padded to 1296 B (=324 words, 81*16B -> distinct 16B bank groups per s)
#define SLICE_WORDS 324
#define COMB_WORDS  (NSLICE * SLICE_WORDS)   // 1296 words = 5184 B

__device__ __forceinline__ float lo32(unsigned long long v) {
    return __uint_as_float((unsigned)(v & 0xffffffffull));
}
__device__ __forceinline__ float hi32(unsigned long long v) {
    return __uint_as_float((unsigned)(v >> 32));
}
__device__ __forceinline__ unsigned long long pk2(float a, float b) {
    return (unsigned long long)__float_as_uint(a) |
           ((unsigned long long)__float_as_uint(b) << 32);
}
__device__ __forceinline__ uint32_t s2u(const void* p) {
    uint32_t a;
    asm("{ .reg .u64 t; cvta.to.shared.u64 t, %1; cvt.u32.u64 %0, t; }"
        : "=r"(a) : "l"(p));
    return a;
}
__device__ __forceinline__ uint32_t mapa_peer(uint32_t laddr, uint32_t peer) {
    uint32_t r;
    asm("mapa.shared::cluster.u32 %0, %1, %2;" : "=r"(r) : "r"(laddr), "r"(peer));
    return r;
}
__device__ __forceinline__ void st_remote_f32(uint32_t raddr, float v) {
    asm volatile("st.shared::cluster.f32 [%0], %1;" :: "r"(raddr), "f"(v) : "memory");
}

// word index inside one comb buffer for logical (k, b)
__device__ __forceinline__ int comb_word(int k, int b) {
    int s  = k / KSLICE;
    int ii = k % KSLICE;
    return s * SLICE_WORDS + (ii >> 1) * 8 + b * 2 + (ii & 1);
}

__global__ void __launch_bounds__(THREADS, 1) __cluster_dims__(2, 1, 1)
rnn_seq_kernel(const float* __restrict__ x,    // (T, B, F)
               const float* __restrict__ W0,   // (H, F+H)
               const float* __restrict__ b0,   // (H)
               const float* __restrict__ Wfc,  // (1, H)
               const float* __restrict__ bfc,  // (1)
               float* __restrict__ out)        // (B, T)
{
    __shared__ __align__(16) float comb[2][COMB_WORDS];
    __shared__ float red[16][4];
    __shared__ float outslot[2][2][4];   // [parity][rank][batch]

    const int tid = threadIdx.x;
    const int s   = tid & 3;             // k-slice / batch lane for tanh
    const int jl  = tid >> 2;            // 0..127 local hidden unit

    uint32_t rank;
    asm("mov.u32 %0, %%cluster_ctarank;" : "=r"(rank));
    const int cluster_id = blockIdx.x >> 1;
    const int j  = (int)rank * 128 + jl;       // global hidden unit
    const int bg = cluster_id * NB;            // first batch of this cluster

    // ---- weights: this thread owns W0[j][80s .. 80s+80) as 40 packed f32x2 pairs ----
    unsigned long long w[NPAIR];
    {
        const float4* wp = reinterpret_cast<const float4*>(
            W0 + (size_t)j * KDIM + s * KSLICE);
        #pragma unroll
        for (int q = 0; q < NPAIR / 2; ++q) {
            float4 v = wp[q];
            w[2 * q]     = pk2(v.x, v.y);
            w[2 * q + 1] = pk2(v.z, v.w);
        }
    }
    const float b0j  = b0[j];
    const float wfcj = Wfc[j];
    const float bfc0 = bfc[0];

    // zero buffer 0 (h region must be 0 for t=0; x region overwritten anyway)
    for (int idx = tid; idx < COMB_WORDS; idx += THREADS) comb[0][idx] = 0.f;

    // ---- precomputed addresses for the h write (k = FEAT + j, batch = s) ----
    const int wordh = comb_word(FEAT + j, s);
    float* const hloc[2] = { &comb[0][wordh], &comb[1][wordh] };
    const uint32_t hrem[2] = {
        mapa_peer(s2u(&comb[0][wordh]), rank ^ 1u),
        mapa_peer(s2u(&comb[1][wordh]), rank ^ 1u)
    };
    // remote outslot address (rank 1 writes into rank 0's outslot[par][1][tid])
    uint32_t osrem[2] = { 0u, 0u };
    if (tid < 4) {
        osrem[0] = mapa_peer(s2u(&outslot[0][1][tid]), 0u);
        osrem[1] = mapa_peer(s2u(&outslot[1][1][tid]), 0u);
    }

    // ---- x prefetch state (threads 0..255 each own one (b, f) element) ----
    float xval = 0.f;
    int xb = 0, xf = 0, xword = 0;
    if (tid < NB * FEAT) {
        xb = tid >> 6;           // 0..3
        xf = tid & 63;           // 0..63
        xword = comb_word(xf, xb);
        xval  = x[((size_t)0 * BATCH + (bg + xb)) * FEAT + xf];   // x_0
    }

    int cur = 0, par = 0;

    for (int t = 0; t < T_STEPS; ++t) {
        // deposit prefetched x_t into current buffer
        if (tid < NB * FEAT) comb[cur][xword] = xval;
        __syncthreads();

        // prefetch x_{t+1} (latency hidden behind the dot products)
        if (tid < NB * FEAT && (t + 1) < T_STEPS)
            xval = x[((size_t)(t + 1) * BATCH + (bg + xb)) * FEAT + xf];

        // ---- main dot products: 80 k-values x 4 batches via packed FFMA2 ----
        unsigned long long a0 = 0ull, a1 = 0ull, a2 = 0ull, a3 = 0ull;
        const ulonglong2* cb = reinterpret_cast<const ulonglong2*>(
            &comb[cur][s * SLICE_WORDS]);
        #pragma unroll
        for (int p = 0; p < NPAIR; ++p) {
            ulonglong2 c01 = cb[2 * p];        // k-pair for batches 0,1
            ulonglong2 c23 = cb[2 * p + 1];    // k-pair for batches 2,3
            asm("fma.rn.f32x2 %0, %1, %2, %0;" : "+l"(a0) : "l"(w[p]), "l"(c01.x));
            asm("fma.rn.f32x2 %0, %1, %2, %0;" : "+l"(a1) : "l"(w[p]), "l"(c01.y));
            asm("fma.rn.f32x2 %0, %1, %2, %0;" : "+l"(a2) : "l"(w[p]), "l"(c23.x));
            asm("fma.rn.f32x2 %0, %1, %2, %0;" : "+l"(a3) : "l"(w[p]), "l"(c23.y));
        }
        float s0 = lo32(a0) + hi32(a0);
        float s1 = lo32(a1) + hi32(a1);
        float s2 = lo32(a2) + hi32(a2);
        float s3 = lo32(a3) + hi32(a3);

        // reduce over the 4 k-slices (lane bits 0..1)
        s0 += __shfl_xor_sync(0xffffffffu, s0, 1);
        s1 += __shfl_xor_sync(0xffffffffu, s1, 1);
        s2 += __shfl_xor_sync(0xffffffffu, s2, 1);
        s3 += __shfl_xor_sync(0xffffffffu, s3, 1);
        s0 += __shfl_xor_sync(0xffffffffu, s0, 2);
        s1 += __shfl_xor_sync(0xffffffffu, s1, 2);
        s2 += __shfl_xor_sync(0xffffffffu, s2, 2);
        s3 += __shfl_xor_sync(0xffffffffu, s3, 2);

        // lane s handles batch b = s: accurate tanh via exp identity
        float pre = s0;
        if (s == 1) pre = s1;
        if (s == 2) pre = s2;
        if (s == 3) pre = s3;
        pre = pre + b0j;
        pre = fminf(fmaxf(pre, -15.f), 15.f);
        float e = __expf(2.f * pre);
        float h = 1.f - __fdividef(2.f, e + 1.f);

        // write h into NEXT buffer: local + peer DSMEM
        const int nxt = cur ^ 1;
        *hloc[nxt] = h;
        st_remote_f32(hrem[nxt], h);

        // output partial: reduce h*Wfc over this warp's 8 hidden units (lane bits 2..4)
        float po = h * wfcj;
        po += __shfl_xor_sync(0xffffffffu, po, 4);
        po += __shfl_xor_sync(0xffffffffu, po, 8);
        po += __shfl_xor_sync(0xffffffffu, po, 16);
        if ((tid & 31) < 4) red[tid >> 5][s] = po;   // lanes 0..3 carry b=0..3
        __syncthreads();

        if (tid < 4) {
            float acc = 0.f;
            #pragma unroll
            for (int wn = 0; wn < 16; ++wn) acc += red[wn][tid];
            if (rank == 0) outslot[par][0][tid] = acc;
            else           st_remote_f32(osrem[par], acc);
        }

        // cluster barrier: release my h + out-partial writes, acquire peer's
        asm volatile("barrier.cluster.arrive.aligned;" ::: "memory");
        asm volatile("barrier.cluster.wait.aligned;"  ::: "memory");

        if (rank == 0 && tid < 4) {
            float o = outslot[par][0][tid] + outslot[par][1][tid] + bfc0;
            out[(size_t)(bg + tid) * T_STEPS + t] = o;
        }

        cur = nxt;
        par ^= 1;
    }
}

extern "C" void kernel_launch(void* const* d_in, const int* in_sizes, int n_in,
                              void* d_out, int out_size) {
    const float* x   = (const float*)d_in[0];
    const float* W0  = (const float*)d_in[1];
    const float* b0  = (const float*)d_in[2];
    const float* Wfc = (const float*)d_in[3];
    const float* bfc = (const float*)d_in[4];
    float* out = (float*)d_out;
    (void)in_sizes; (void)n_in; (void)out_size;

    // 64 clusters of 2 CTAs (static __cluster_dims__), 4 batches per cluster
    rnn_seq_kernel<<<128, THREADS>>>(x, W0, b0, Wfc, bfc, out);
}

// round 4
// speedup vs baseline: 1.8023x; 1.8023x over previous
#include <cuda_runtime.h>
#include <cstdint>
#include <cstddef>

// Problem constants
#define T_STEPS 2048
#define BATCH   256
#define FEAT    64
#define KDIM    320            // FEAT + HID
#define THREADS 256
#define NSL     8              // k-slices (s = lane & 7)
#define KSL     40             // k per slice
#define NKP     20             // kpairs per slice
#define SLW     164            // slice stride in words (656 B; 656 mod 128 = 16 -> 8 distinct bank groups)
#define BUFW    (NSL * SLW)    // 1312 words per buffer

__device__ __forceinline__ float lo32(unsigned long long v) {
    return __uint_as_float((unsigned)(v & 0xffffffffull));
}
__device__ __forceinline__ float hi32(unsigned long long v) {
    return __uint_as_float((unsigned)(v >> 32));
}
__device__ __forceinline__ unsigned long long pk2(float a, float b) {
    return (unsigned long long)__float_as_uint(a) |
           ((unsigned long long)__float_as_uint(b) << 32);
}
__device__ __forceinline__ void fma2(unsigned long long& acc,
                                     unsigned long long w, unsigned long long c) {
    asm("fma.rn.f32x2 %0, %1, %2, %0;" : "+l"(acc) : "l"(w), "l"(c));
}
__device__ __forceinline__ unsigned long long add2(unsigned long long a,
                                                   unsigned long long b) {
    unsigned long long r;
    asm("add.rn.f32x2 %0, %1, %2;" : "=l"(r) : "l"(a), "l"(b));
    return r;
}
__device__ __forceinline__ uint32_t s2u(const void* p) {
    uint32_t a;
    asm("{ .reg .u64 t; cvta.to.shared.u64 t, %1; cvt.u32.u64 %0, t; }"
        : "=r"(a) : "l"(p));
    return a;
}
__device__ __forceinline__ uint32_t mapa_peer(uint32_t laddr, uint32_t peer) {
    uint32_t r;
    asm("mapa.shared::cluster.u32 %0, %1, %2;" : "=r"(r) : "r"(laddr), "r"(peer));
    return r;
}
__device__ __forceinline__ void st_remote_f32(uint32_t raddr, float v) {
    asm volatile("st.shared::cluster.f32 [%0], %1;" :: "r"(raddr), "f"(v) : "memory");
}

// word index inside one comb buffer for logical (k, b)
__device__ __forceinline__ int cword(int k, int b) {
    int s  = k / KSL;
    int kk = k % KSL;
    return s * SLW + (kk >> 1) * 8 + b * 2 + (kk & 1);
}

__global__ void __launch_bounds__(THREADS, 1) __cluster_dims__(2, 1, 1)
rnn_seq_kernel(const float* __restrict__ x,    // (T, B, F)
               const float* __restrict__ W0,   // (H, F+H)
               const float* __restrict__ b0,   // (H)
               const float* __restrict__ Wfc,  // (1, H)
               const float* __restrict__ bfc,  // (1)
               float* __restrict__ out)        // (B, T)
{
    __shared__ __align__(16) float comb[2][BUFW];
    __shared__ float red[8][4];
    __shared__ float outslot[2][2][4];   // [parity][rank][batch]

    const int tid  = threadIdx.x;
    const int w    = tid >> 5;            // warp 0..7
    const int lane = tid & 31;
    const int s    = lane & 7;            // k-slice 0..7
    const int gq   = lane >> 3;           // j-group quadrant within warp
    const int g    = w * 4 + gq;          // j-group 0..31 (4 j's each)

    uint32_t rank;
    asm("mov.u32 %0, %%cluster_ctarank;" : "=r"(rank));
    const int cluster_id = blockIdx.x >> 1;
    const int bg = cluster_id * 4;                 // first batch of this cluster
    const int j0 = (int)rank * 128 + g * 4;        // first global hidden unit of group

    // ---- weights: thread owns W0[j0..j0+4)[40s..40s+40) as 80 packed f32x2 ----
    unsigned long long wreg[4 * NKP];
    #pragma unroll
    for (int jj = 0; jj < 4; ++jj) {
        const float4* wp = reinterpret_cast<const float4*>(
            W0 + (size_t)(j0 + jj) * KDIM + s * KSL);
        #pragma unroll
        for (int q = 0; q < NKP / 2; ++q) {
            float4 v = wp[q];
            wreg[jj * NKP + 2 * q]     = pk2(v.x, v.y);
            wreg[jj * NKP + 2 * q + 1] = pk2(v.z, v.w);
        }
    }

    // After butterfly, this lane owns h for j = j0 + (s>>1), batches bp, bp+1
    const int jmine = j0 + (s >> 1);
    const int bp    = (s & 1) * 2;
    const float b0j  = b0[jmine];
    const float wfcj = Wfc[jmine];
    const float bfc0 = bfc[0];

    // h write targets (word index within a buffer) for (k = 64 + jmine, b)
    const int hw0 = cword(64 + jmine, bp);
    const int hw1 = cword(64 + jmine, bp + 1);
    const uint32_t hr0[2] = { mapa_peer(s2u(&comb[0][hw0]), rank ^ 1u),
                              mapa_peer(s2u(&comb[1][hw0]), rank ^ 1u) };
    const uint32_t hr1[2] = { mapa_peer(s2u(&comb[0][hw1]), rank ^ 1u),
                              mapa_peer(s2u(&comb[1][hw1]), rank ^ 1u) };

    uint32_t osrem[2] = { 0u, 0u };
    if (tid < 4) {
        osrem[0] = mapa_peer(s2u(&outslot[0][1][tid]), 0u);
        osrem[1] = mapa_peer(s2u(&outslot[1][1][tid]), 0u);
    }

    // ---- x deposit: 256 threads each own one (b, f) element ----
    const int xb = tid >> 6;             // 0..3
    const int xf = tid & 63;             // 0..63
    const int xword = cword(xf, xb);

    // zero both buffers (buffer0 h-region must be 0 for t=0)
    for (int i = tid; i < 2 * BUFW; i += THREADS)
        (&comb[0][0])[i] = 0.f;
    __syncthreads();
    comb[0][xword] = x[((size_t)0 * BATCH + (bg + xb)) * FEAT + xf];     // x_0
    float xval     = x[((size_t)1 * BATCH + (bg + xb)) * FEAT + xf];     // x_1
    const float* xp = x + ((size_t)2 * BATCH + (bg + xb)) * FEAT + xf;   // -> x_2
    __syncthreads();

    int cur = 0, par = 0;

    for (int t = 0; t < T_STEPS; ++t) {
        // ---- dot products: 20 kpairs x 4 j x 4 b via packed FFMA2 ----
        unsigned long long a[16];
        #pragma unroll
        for (int i = 0; i < 16; ++i) a[i] = 0ull;

        const ulonglong2* cb = reinterpret_cast<const ulonglong2*>(
            &comb[cur][s * SLW]);
        #pragma unroll
        for (int pp = 0; pp < NKP; ++pp) {
            ulonglong2 c01 = cb[2 * pp];        // batches 0,1 kpair
            ulonglong2 c23 = cb[2 * pp + 1];    // batches 2,3 kpair
            #pragma unroll
            for (int jj = 0; jj < 4; ++jj) {
                fma2(a[jj * 4 + 0], wreg[jj * NKP + pp], c01.x);
                fma2(a[jj * 4 + 1], wreg[jj * NKP + pp], c01.y);
                fma2(a[jj * 4 + 2], wreg[jj * NKP + pp], c23.x);
                fma2(a[jj * 4 + 3], wreg[jj * NKP + pp], c23.y);
            }
        }

        // ---- value-halving butterfly over the 8 slice lanes ----
        #pragma unroll
        for (int k = 0; k < 8; ++k) {
            unsigned long long t1 = __shfl_xor_sync(0xffffffffu, a[k],     4);
            unsigned long long t2 = __shfl_xor_sync(0xffffffffu, a[8 + k], 4);
            a[k] = (s & 4) ? add2(a[8 + k], t2) : add2(a[k], t1);
        }
        #pragma unroll
        for (int k = 0; k < 4; ++k) {
            unsigned long long t1 = __shfl_xor_sync(0xffffffffu, a[k],     2);
            unsigned long long t2 = __shfl_xor_sync(0xffffffffu, a[4 + k], 2);
            a[k] = (s & 2) ? add2(a[4 + k], t2) : add2(a[k], t1);
        }
        #pragma unroll
        for (int k = 0; k < 2; ++k) {
            unsigned long long t1 = __shfl_xor_sync(0xffffffffu, a[k],     1);
            unsigned long long t2 = __shfl_xor_sync(0xffffffffu, a[2 + k], 1);
            a[k] = (s & 1) ? add2(a[2 + k], t2) : add2(a[k], t1);
        }

        // two (j, b) results per lane: accurate tanh via exp identity
        float pre0 = lo32(a[0]) + hi32(a[0]) + b0j;
        float pre1 = lo32(a[1]) + hi32(a[1]) + b0j;
        pre0 = fminf(fmaxf(pre0, -15.f), 15.f);
        pre1 = fminf(fmaxf(pre1, -15.f), 15.f);
        float e0 = __expf(2.f * pre0);
        float e1 = __expf(2.f * pre1);
        float h0 = 1.f - __fdividef(2.f, e0 + 1.f);
        float h1 = 1.f - __fdividef(2.f, e1 + 1.f);

        // write h into NEXT buffer: local + peer DSMEM
        const int nxt = cur ^ 1;
        comb[nxt][hw0] = h0;
        comb[nxt][hw1] = h1;
        st_remote_f32(hr0[nxt], h0);
        st_remote_f32(hr1[nxt], h1);

        // deposit x_{t+1} into next buffer (disjoint words); prefetch x_{t+2}
        comb[nxt][xword] = xval;
        if (t < T_STEPS - 2) { xval = *xp; xp += (size_t)BATCH * FEAT; }

        // output partials: reduce h*Wfc over the warp's 16 j per batch-pair
        float po0 = h0 * wfcj;
        float po1 = h1 * wfcj;
        #pragma unroll
        for (int d = 2; d < 32; d <<= 1) {
            po0 += __shfl_xor_sync(0xffffffffu, po0, d);
            po1 += __shfl_xor_sync(0xffffffffu, po1, d);
        }
        if (gq == 0 && (s >> 1) == 0) {
            red[w][(s & 1) * 2 + 0] = po0;
            red[w][(s & 1) * 2 + 1] = po1;
        }
        __syncthreads();

        if (tid < 4) {
            float acc = 0.f;
            #pragma unroll
            for (int wn = 0; wn < 8; ++wn) acc += red[wn][tid];
            if (rank == 0) outslot[par][0][tid] = acc;
            else           st_remote_f32(osrem[par], acc);
        }

        // cluster barrier: release my h + out-partial writes, acquire peer's
        asm volatile("barrier.cluster.arrive.aligned;" ::: "memory");
        asm volatile("barrier.cluster.wait.aligned;"  ::: "memory");

        if (rank == 0 && tid < 4) {
            out[(size_t)(bg + tid) * T_STEPS + t] =
                outslot[par][0][tid] + outslot[par][1][tid] + bfc0;
        }

        cur = nxt;
        par ^= 1;
    }
}

extern "C" void kernel_launch(void* const* d_in, const int* in_sizes, int n_in,
                              void* d_out, int out_size) {
    const float* x   = (const float*)d_in[0];
    const float* W0  = (const float*)d_in[1];
    const float* b0  = (const float*)d_in[2];
    const float* Wfc = (const float*)d_in[3];
    const float* bfc = (const float*)d_in[4];
    float* out = (float*)d_out;
    (void)in_sizes; (void)n_in; (void)out_size;

    // 64 clusters of 2 CTAs (static __cluster_dims__), 4 batches per cluster
    rnn_seq_kernel<<<128, THREADS>>>(x, W0, b0, Wfc, bfc, out);
}

// round 5
// speedup vs baseline: 1.8317x; 1.0163x over previous
#include <cuda_runtime.h>
#include <cstdint>
#include <cstddef>

// Problem constants
#define T_STEPS 2048
#define BATCH   256
#define FEAT    64
#define KDIM    320            // FEAT + HID
#define THREADS 256
#define NSL     8              // k-slices (s = lane & 7)
#define KSL     40             // k per slice
#define NKP     20             // kpairs per slice
#define SLW     164            // slice stride in words (656 B -> 8 distinct 16B bank groups)
#define BUFW    (NSL * SLW)    // 1312 words per buffer

__device__ __forceinline__ float lo32(unsigned long long v) {
    return __uint_as_float((unsigned)(v & 0xffffffffull));
}
__device__ __forceinline__ float hi32(unsigned long long v) {
    return __uint_as_float((unsigned)(v >> 32));
}
__device__ __forceinline__ unsigned long long pk2(float a, float b) {
    return (unsigned long long)__float_as_uint(a) |
           ((unsigned long long)__float_as_uint(b) << 32);
}
__device__ __forceinline__ void fma2(unsigned long long& acc,
                                     unsigned long long w, unsigned long long c) {
    asm("fma.rn.f32x2 %0, %1, %2, %0;" : "+l"(acc) : "l"(w), "l"(c));
}
__device__ __forceinline__ uint32_t s2u(const void* p) {
    uint32_t a;
    asm("{ .reg .u64 t; cvta.to.shared.u64 t, %1; cvt.u32.u64 %0, t; }"
        : "=r"(a) : "l"(p));
    return a;
}
__device__ __forceinline__ uint32_t mapa_peer(uint32_t laddr, uint32_t peer) {
    uint32_t r;
    asm("mapa.shared::cluster.u32 %0, %1, %2;" : "=r"(r) : "r"(laddr), "r"(peer));
    return r;
}
__device__ __forceinline__ void st_remote_f32(uint32_t raddr, float v) {
    asm volatile("st.shared::cluster.f32 [%0], %1;" :: "r"(raddr), "f"(v) : "memory");
}
__device__ __forceinline__ void redg_add(float* p, float v) {
    asm volatile("red.global.add.f32 [%0], %1;" :: "l"(p), "f"(v) : "memory");
}

// word index inside one comb buffer for logical (k, b)
__device__ __forceinline__ int cword(int k, int b) {
    int s  = k / KSL;
    int kk = k % KSL;
    return s * SLW + (kk >> 1) * 8 + b * 2 + (kk & 1);
}

// ---- init kernel: out[b][t] = bfc (REDG partials accumulate on top) ----
__global__ void init_out_kernel(const float* __restrict__ bfc,
                                float* __restrict__ out) {
    int i = blockIdx.x * blockDim.x + threadIdx.x;
    out[i] = bfc[0];
}

__global__ void __launch_bounds__(THREADS, 1) __cluster_dims__(2, 1, 1)
rnn_seq_kernel(const float* __restrict__ x,    // (T, B, F)
               const float* __restrict__ W0,   // (H, F+H)
               const float* __restrict__ b0,   // (H)
               const float* __restrict__ Wfc,  // (1, H)
               float* __restrict__ out)        // (B, T)
{
    __shared__ __align__(16) float comb[2][BUFW];

    const int tid  = threadIdx.x;
    const int w    = tid >> 5;            // warp 0..7
    const int lane = tid & 31;
    const int s    = lane & 7;            // k-slice 0..7
    const int gq   = lane >> 3;           // j-group quadrant within warp
    const int g    = w * 4 + gq;          // j-group 0..31 (4 j's each)

    uint32_t rank;
    asm("mov.u32 %0, %%cluster_ctarank;" : "=r"(rank));
    const int cluster_id = blockIdx.x >> 1;
    const int bg = cluster_id * 4;                 // first batch of this cluster
    const int j0 = (int)rank * 128 + g * 4;        // first global hidden unit of group

    // ---- weights: thread owns W0[j0..j0+4)[40s..40s+40) as 80 packed f32x2 ----
    unsigned long long wreg[4 * NKP];
    #pragma unroll
    for (int jj = 0; jj < 4; ++jj) {
        const float4* wp = reinterpret_cast<const float4*>(
            W0 + (size_t)(j0 + jj) * KDIM + s * KSL);
        #pragma unroll
        for (int q = 0; q < NKP / 2; ++q) {
            float4 v = wp[q];
            wreg[jj * NKP + 2 * q]     = pk2(v.x, v.y);
            wreg[jj * NKP + 2 * q + 1] = pk2(v.z, v.w);
        }
    }

    // After butterfly, this lane owns pre-acts for j = j0 + (s>>1), batches bp, bp+1
    const int jmine = j0 + (s >> 1);
    const int bp    = (s & 1) * 2;
    const float b0j  = b0[jmine];
    const float wfcj = Wfc[jmine];

    // h write targets (word index within a buffer) for (k = 64 + jmine, b)
    const int hw0 = cword(64 + jmine, bp);
    const int hw1 = cword(64 + jmine, bp + 1);
    const uint32_t hr0[2] = { mapa_peer(s2u(&comb[0][hw0]), rank ^ 1u),
                              mapa_peer(s2u(&comb[1][hw0]), rank ^ 1u) };
    const uint32_t hr1[2] = { mapa_peer(s2u(&comb[0][hw1]), rank ^ 1u),
                              mapa_peer(s2u(&comb[1][hw1]), rank ^ 1u) };

    // ---- x deposit: 256 threads each own one (b, f) element ----
    const int xb = tid >> 6;             // 0..3
    const int xf = tid & 63;             // 0..63
    const int xword = cword(xf, xb);

    // zero both buffers (buffer0 h-region must be 0 for t=0)
    for (int i = tid; i < 2 * BUFW; i += THREADS)
        (&comb[0][0])[i] = 0.f;
    __syncthreads();
    comb[0][xword] = x[((size_t)0 * BATCH + (bg + xb)) * FEAT + xf];     // x_0
    float xval     = x[((size_t)1 * BATCH + (bg + xb)) * FEAT + xf];     // x_1
    const float* xp = x + ((size_t)2 * BATCH + (bg + xb)) * FEAT + xf;   // -> x_2

    // full cluster sync: peer must finish zeroing before our t=0 remote h stores
    asm volatile("barrier.cluster.arrive.aligned;" ::: "memory");
    asm volatile("barrier.cluster.wait.aligned;"  ::: "memory");

    int cur = 0;

    for (int t = 0; t < T_STEPS; ++t) {
        // ---- dot products: 20 kpairs x 4 j x 4 b via packed FFMA2 ----
        unsigned long long a[16];
        #pragma unroll
        for (int i = 0; i < 16; ++i) a[i] = 0ull;

        const ulonglong2* cb = reinterpret_cast<const ulonglong2*>(
            &comb[cur][s * SLW]);
        #pragma unroll
        for (int pp = 0; pp < NKP; ++pp) {
            ulonglong2 c01 = cb[2 * pp];        // batches 0,1 kpair
            ulonglong2 c23 = cb[2 * pp + 1];    // batches 2,3 kpair
            #pragma unroll
            for (int jj = 0; jj < 4; ++jj) {
                fma2(a[jj * 4 + 0], wreg[jj * NKP + pp], c01.x);
                fma2(a[jj * 4 + 1], wreg[jj * NKP + pp], c01.y);
                fma2(a[jj * 4 + 2], wreg[jj * NKP + pp], c23.x);
                fma2(a[jj * 4 + 3], wreg[jj * NKP + pp], c23.y);
            }
        }

        // fold k-pairs to scalars: v[jj*4 + b]
        float v[16];
        #pragma unroll
        for (int i = 0; i < 16; ++i) v[i] = lo32(a[i]) + hi32(a[i]);

        // ---- value-halving butterfly over the 8 slice lanes (32-bit) ----
        #pragma unroll
        for (int k = 0; k < 8; ++k) {
            float t1 = __shfl_xor_sync(0xffffffffu, v[k],     4);
            float t2 = __shfl_xor_sync(0xffffffffu, v[8 + k], 4);
            v[k] = (s & 4) ? (v[8 + k] + t2) : (v[k] + t1);
        }
        #pragma unroll
        for (int k = 0; k < 4; ++k) {
            float t1 = __shfl_xor_sync(0xffffffffu, v[k],     2);
            float t2 = __shfl_xor_sync(0xffffffffu, v[4 + k], 2);
            v[k] = (s & 2) ? (v[4 + k] + t2) : (v[k] + t1);
        }
        {
            float t1 = __shfl_xor_sync(0xffffffffu, v[0], 1);
            float t2 = __shfl_xor_sync(0xffffffffu, v[2], 1);
            float t3 = __shfl_xor_sync(0xffffffffu, v[1], 1);
            float t4 = __shfl_xor_sync(0xffffffffu, v[3], 1);
            v[0] = (s & 1) ? (v[2] + t2) : (v[0] + t1);
            v[1] = (s & 1) ? (v[3] + t4) : (v[1] + t3);
        }

        // two (j, b) results per lane: accurate tanh via exp identity
        float pre0 = v[0] + b0j;
        float pre1 = v[1] + b0j;
        pre0 = fminf(fmaxf(pre0, -15.f), 15.f);
        pre1 = fminf(fmaxf(pre1, -15.f), 15.f);
        float e0 = __expf(2.f * pre0);
        float e1 = __expf(2.f * pre1);
        float h0 = 1.f - __fdividef(2.f, e0 + 1.f);
        float h1 = 1.f - __fdividef(2.f, e1 + 1.f);

        // write h into NEXT buffer: local + peer DSMEM; deposit x_{t+1}
        const int nxt = cur ^ 1;
        comb[nxt][hw0] = h0;
        comb[nxt][hw1] = h1;
        st_remote_f32(hr0[nxt], h0);
        st_remote_f32(hr1[nxt], h1);
        comb[nxt][xword] = xval;

        // arrive early: release all the stores above to the cluster
        asm volatile("barrier.cluster.arrive.aligned;" ::: "memory");

        // ---- shadow region (hidden under barrier latency) ----
        // prefetch x_{t+2}
        if (t < T_STEPS - 2) { xval = *xp; xp += (size_t)BATCH * FEAT; }

        // output partials: warp-reduce h*Wfc over j (lane bits 1..4), then REDG
        float po0 = h0 * wfcj;
        float po1 = h1 * wfcj;
        #pragma unroll
        for (int d = 2; d < 32; d <<= 1) {
            po0 += __shfl_xor_sync(0xffffffffu, po0, d);
            po1 += __shfl_xor_sync(0xffffffffu, po1, d);
        }
        if (lane < 2) {
            // lane0: (b0,b1), lane1: (b2,b3)
            redg_add(out + (size_t)(bg + lane * 2 + 0) * T_STEPS + t, po0);
            redg_add(out + (size_t)(bg + lane * 2 + 1) * T_STEPS + t, po1);
        }

        // acquire peer's h for the next step
        asm volatile("barrier.cluster.wait.aligned;" ::: "memory");

        cur = nxt;
    }
}

extern "C" void kernel_launch(void* const* d_in, const int* in_sizes, int n_in,
                              void* d_out, int out_size) {
    const float* x   = (const float*)d_in[0];
    const float* W0  = (const float*)d_in[1];
    const float* b0  = (const float*)d_in[2];
    const float* Wfc = (const float*)d_in[3];
    const float* bfc = (const float*)d_in[4];
    float* out = (float*)d_out;
    (void)in_sizes; (void)n_in; (void)out_size;

    // 1) out[b][t] = bfc  (256*2048 = 524288 elements)
    init_out_kernel<<<(BATCH * T_STEPS) / 256, 256>>>(bfc, out);
    // 2) 64 clusters of 2 CTAs (static __cluster_dims__), 4 batches per cluster
    rnn_seq_kernel<<<128, THREADS>>>(x, W0, b0, Wfc, out);
}

// round 6
// speedup vs baseline: 1.9686x; 1.0747x over previous
#include <cuda_runtime.h>
#include <cstdint>
#include <cstddef>

// Problem constants
#define T_STEPS 2048
#define BATCH   256
#define FEAT    64
#define KDIM    320            // FEAT + HID
#define THREADS 512
#define NWARP   16

// SMEM layout (dynamic):
//  [0, WSM_WORDS)        : smem-resident weight half (jj=2,3), 160KB
//  [WSM_WORDS, +2*BUFW)  : comb double buffer
#define WSM_WORDS (NWARP * 20 * 128)     // 16 warps * 20 iters * 512B = 160KB -> 40960 words
#define SLICEW 44                         // words per k-slice (40 data + 4 pad -> distinct bank groups)
#define BROWW  356                        // words per batch row (8 slices * 44 + 4 pad)
#define BUFW   (2 * BROWW)                // 712 words per buffer (2 batches)
#define COMB_WORDS (2 * BUFW)             // 1424
#define SMEM_BYTES ((WSM_WORDS + COMB_WORDS) * 4)   // 169,536 B

__device__ __forceinline__ float lo32(unsigned long long v) {
    return __uint_as_float((unsigned)(v & 0xffffffffull));
}
__device__ __forceinline__ float hi32(unsigned long long v) {
    return __uint_as_float((unsigned)(v >> 32));
}
__device__ __forceinline__ unsigned long long pk2(float a, float b) {
    return (unsigned long long)__float_as_uint(a) |
           ((unsigned long long)__float_as_uint(b) << 32);
}
__device__ __forceinline__ void fma2(unsigned long long& acc,
                                     unsigned long long w, unsigned long long c) {
    asm("fma.rn.f32x2 %0, %1, %2, %0;" : "+l"(acc) : "l"(w), "l"(c));
}
__device__ __forceinline__ void redg_add(float* p, float v) {
    asm volatile("red.global.add.f32 [%0], %1;" :: "l"(p), "f"(v) : "memory");
}

// word index within one comb buffer for (b, k)
__device__ __forceinline__ int cword(int b, int k) {
    return b * BROWW + (k / 40) * SLICEW + (k % 40);
}

// ---- init kernel: out[b][t] = bfc (REDG partials accumulate on top) ----
__global__ void init_out_kernel(const float* __restrict__ bfc,
                                float* __restrict__ out) {
    int i = blockIdx.x * blockDim.x + threadIdx.x;
    out[i] = bfc[0];
}

__global__ void __launch_bounds__(THREADS, 1)
rnn_seq_kernel(const float* __restrict__ x,    // (T, B, F)
               const float* __restrict__ W0,   // (H, F+H)
               const float* __restrict__ b0,   // (H)
               const float* __restrict__ Wfc,  // (1, H)
               float* __restrict__ out)        // (B, T)
{
    extern __shared__ float smem[];
    float* const wsm  = smem;
    float* const comb = smem + WSM_WORDS;

    const int tid  = threadIdx.x;
    const int w    = tid >> 5;            // warp 0..15
    const int lane = tid & 31;
    const int s    = lane & 7;            // k-slice 0..7 (40 k each)
    const int jg   = tid >> 3;            // j-group 0..63 (4 j each)
    const int bg   = blockIdx.x * 2;      // first batch of this CTA

    // ---- RF weights: jj = 0,1 -> W0[jg*4+jj][40s..40s+40) as 20 f32x2 each ----
    unsigned long long wr[40];
    #pragma unroll
    for (int jj = 0; jj < 2; ++jj) {
        const float4* wp = reinterpret_cast<const float4*>(
            W0 + (size_t)(jg * 4 + jj) * KDIM + s * 40);
        #pragma unroll
        for (int q = 0; q < 10; ++q) {
            float4 v = wp[q];
            wr[jj * 20 + 2 * q]     = pk2(v.x, v.y);
            wr[jj * 20 + 2 * q + 1] = pk2(v.z, v.w);
        }
    }
    // ---- SMEM weights: jj = 2,3. Layout: [warp][iter 0..19][lane] float4 ----
    {
        float4* dst = reinterpret_cast<float4*>(wsm) + (size_t)w * 640 + lane;
        #pragma unroll
        for (int jj = 0; jj < 2; ++jj) {
            const float4* wp = reinterpret_cast<const float4*>(
                W0 + (size_t)(jg * 4 + 2 + jj) * KDIM + s * 40);
            #pragma unroll
            for (int q = 0; q < 10; ++q)
                dst[(jj * 10 + q) * 32] = wp[q];
        }
    }

    // After butterfly: lane owns (j = jg*4 + (s>>1), b = s&1)
    const int jm = jg * 4 + (s >> 1);
    const int bm = s & 1;
    const float b0j  = b0[jm];
    const float wfcj = Wfc[jm];
    const int hword  = cword(bm, FEAT + jm);

    // x deposit: threads 0..127 each own one (b, f)
    const bool xown = tid < 2 * FEAT;
    const int xb = (tid >> 6) & 1;
    const int xf = tid & 63;
    const int xword = cword(xb, xf);

    // zero both comb buffers (h region of buf0 must be 0 at t=0)
    for (int i = tid; i < COMB_WORDS; i += THREADS) comb[i] = 0.f;
    __syncthreads();

    float xval = 0.f;
    const float* xp = x + ((size_t)2 * BATCH + bg + xb) * FEAT + xf;   // -> x_2
    if (xown) {
        comb[xword] = x[((size_t)0 * BATCH + bg + xb) * FEAT + xf];    // x_0
        xval        = x[((size_t)1 * BATCH + bg + xb) * FEAT + xf];    // x_1
    }
    __syncthreads();

    const ulonglong2* const WS =
        reinterpret_cast<const ulonglong2*>(wsm) + (size_t)w * 640 + lane;

    int cur = 0;

    for (int t = 0; t < T_STEPS; ++t) {
        // ---- dot products: 10 float4-chunks x 4 j x 2 b ----
        unsigned long long acc[8];
        #pragma unroll
        for (int i = 0; i < 8; ++i) acc[i] = 0ull;

        const ulonglong2* A0 = reinterpret_cast<const ulonglong2*>(
            comb + cur * BUFW + s * SLICEW);
        const ulonglong2* A1 = reinterpret_cast<const ulonglong2*>(
            comb + cur * BUFW + BROWW + s * SLICEW);

        #pragma unroll
        for (int q = 0; q < 10; ++q) {
            ulonglong2 a0 = A0[q];             // acts kpairs (2q,2q+1), batch 0
            ulonglong2 a1 = A1[q];             // batch 1
            ulonglong2 wc = WS[q * 32];        // weights jj=2
            ulonglong2 wd = WS[(10 + q) * 32]; // weights jj=3
            fma2(acc[0], wr[2 * q],      a0.x); fma2(acc[0], wr[2 * q + 1],      a0.y);
            fma2(acc[1], wr[2 * q],      a1.x); fma2(acc[1], wr[2 * q + 1],      a1.y);
            fma2(acc[2], wr[20 + 2 * q], a0.x); fma2(acc[2], wr[20 + 2 * q + 1], a0.y);
            fma2(acc[3], wr[20 + 2 * q], a1.x); fma2(acc[3], wr[20 + 2 * q + 1], a1.y);
            fma2(acc[4], wc.x, a0.x);           fma2(acc[4], wc.y, a0.y);
            fma2(acc[5], wc.x, a1.x);           fma2(acc[5], wc.y, a1.y);
            fma2(acc[6], wd.x, a0.x);           fma2(acc[6], wd.y, a0.y);
            fma2(acc[7], wd.x, a1.x);           fma2(acc[7], wd.y, a1.y);
        }

        // fold k-pairs: v[m], m = jj*2 + b
        float v[8];
        #pragma unroll
        for (int i = 0; i < 8; ++i) v[i] = lo32(acc[i]) + hi32(acc[i]);

        // ---- value-halving butterfly over the 8 slice lanes ----
        #pragma unroll
        for (int k = 0; k < 4; ++k) {
            float t1 = __shfl_xor_sync(0xffffffffu, v[k],     4);
            float t2 = __shfl_xor_sync(0xffffffffu, v[4 + k], 4);
            v[k] = (s & 4) ? (v[4 + k] + t2) : (v[k] + t1);
        }
        #pragma unroll
        for (int k = 0; k < 2; ++k) {
            float t1 = __shfl_xor_sync(0xffffffffu, v[k],     2);
            float t2 = __shfl_xor_sync(0xffffffffu, v[2 + k], 2);
            v[k] = (s & 2) ? (v[2 + k] + t2) : (v[k] + t1);
        }
        {
            float t1 = __shfl_xor_sync(0xffffffffu, v[0], 1);
            float t2 = __shfl_xor_sync(0xffffffffu, v[1], 1);
            v[0] = (s & 1) ? (v[1] + t2) : (v[0] + t1);
        }

        // lane owns (jm, bm): accurate tanh via exp identity
        float pre = v[0] + b0j;
        pre = fminf(fmaxf(pre, -15.f), 15.f);
        float e = __expf(2.f * pre);
        float h = 1.f - __fdividef(2.f, e + 1.f);

        // write h + x_{t+1} into NEXT buffer (local smem only)
        const int nxt = cur ^ 1;
        comb[nxt * BUFW + hword] = h;
        if (xown) comb[nxt * BUFW + xword] = xval;

        __syncthreads();   // single barrier per step

        // ---- post-barrier work (overlaps next step's lead-in) ----
        if (xown && (t + 2) < T_STEPS) { xval = *xp; xp += (size_t)BATCH * FEAT; }

        // output partials: sum h*Wfc over j within warp (parity-preserving)
        float po = h * wfcj;
        po += __shfl_xor_sync(0xffffffffu, po, 2);
        po += __shfl_xor_sync(0xffffffffu, po, 4);
        po += __shfl_xor_sync(0xffffffffu, po, 8);
        po += __shfl_xor_sync(0xffffffffu, po, 16);
        if (lane < 2)
            redg_add(out + (size_t)(bg + lane) * T_STEPS + t, po);

        cur = nxt;
    }
}

extern "C" void kernel_launch(void* const* d_in, const int* in_sizes, int n_in,
                              void* d_out, int out_size) {
    const float* x   = (const float*)d_in[0];
    const float* W0  = (const float*)d_in[1];
    const float* b0  = (const float*)d_in[2];
    const float* Wfc = (const float*)d_in[3];
    const float* bfc = (const float*)d_in[4];
    float* out = (float*)d_out;
    (void)in_sizes; (void)n_in; (void)out_size;

    // 1) out[b][t] = bfc  (256*2048 elements)
    init_out_kernel<<<(BATCH * T_STEPS) / 256, 256>>>(bfc, out);

    // 2) single-CTA-per-batch-pair RNN: 128 CTAs, 512 threads, 169.5KB dyn smem
    cudaFuncSetAttribute(rnn_seq_kernel,
                         cudaFuncAttributeMaxDynamicSharedMemorySize, SMEM_BYTES);
    rnn_seq_kernel<<<BATCH / 2, THREADS, SMEM_BYTES>>>(x, W0, b0, Wfc, out);
}